// round 10
// baseline (speedup 1.0000x reference)
#include <cuda_runtime.h>
#include <math.h>

#define N_PTS 30000
#define M_AT  8000
#define D     16
#define KNN   16
#define NK    (N_PTS*KNN)
#define BN_EPS 1e-5
#define SLOPE 0.2f
#define NC    32
#define NBKT  (NC*NC*NC)                     // 32768 cells of 0.25
#define NWARP ((N_PTS + 31) / 32)            // 938
#define NBLK_K 118                           // ceil(944 warps / 8)

// ---- scratch (device globals) ----
__device__ float4 g_atoms[M_AT];          // sorted: x,y,z,|y|^2
__device__ float4 g_t4[M_AT*4];           // sorted transformed atom feats
__device__ int    g_aperm[M_AT];          // sorted slot -> original atom
__device__ int    g_pperm[N_PTS];         // sorted slot -> original point
__device__ int    g_acnt[NBKT], g_aoff[NBKT], g_awork[NBKT];
__device__ int    g_pcnt[NBKT], g_poff[NBKT], g_pwork[NBKT];
__device__ int    g_idx[NK];              // knn indices (sorted-slot space)
__device__ float  g_invd[NK];
__device__ float4 g_h1v[NK*4];
__device__ float4 g_h2v[NK*4];
__device__ float  g_fx1[N_PTS*D];
__device__ double g_stats[4*D];
__device__ float4 g_A1v[4], g_B1v[4], g_A2v[4], g_B2v[4];

__device__ __forceinline__ float lrelu(float x){ return x > 0.f ? x : SLOPE*x; }

__device__ __forceinline__ int cell1(float x){
  return (int)fminf(fmaxf((x+4.f)*4.f, 0.f), 31.f);
}
__device__ __forceinline__ int bucket_of(float x, float y, float z){
  return (cell1(x)<<10) | (cell1(y)<<5) | cell1(z);
}

// ---- zero counters + stats ----
__global__ void __launch_bounds__(1024) k_zero(){
  int i = blockIdx.x*1024 + threadIdx.x;
  if (i < NBKT) g_acnt[i] = 0; else g_pcnt[i-NBKT] = 0;
  if (blockIdx.x == 0 && threadIdx.x < 4*D) g_stats[threadIdx.x] = 0.0;
}

// ---- count atoms and points in one launch ----
__global__ void k_count_both(const float* __restrict__ atom_xyz,
                             const float* __restrict__ xyz){
  int i = blockIdx.x*blockDim.x + threadIdx.x;
  if (i < M_AT){
    atomicAdd(&g_acnt[bucket_of(atom_xyz[i*3], atom_xyz[i*3+1], atom_xyz[i*3+2])], 1);
  } else if (i < M_AT + N_PTS){
    int p = i - M_AT;
    atomicAdd(&g_pcnt[bucket_of(xyz[p*3], xyz[p*3+1], xyz[p*3+2])], 1);
  }
}

// ---- exclusive scan of 32768 ints; block 0 = atoms, block 1 = points ----
__global__ void __launch_bounds__(1024) k_scan2(){
  const int* cnt = blockIdx.x ? g_pcnt : g_acnt;
  int* off  = blockIdx.x ? g_poff  : g_aoff;
  int* work = blockIdx.x ? g_pwork : g_awork;
  __shared__ int ws[32];
  int t = threadIdx.x;
  int v[32]; int tsum = 0;
  #pragma unroll
  for (int i=0;i<32;i++){ v[i] = cnt[t*32+i]; tsum += v[i]; }
  int lane = t&31, w = t>>5;
  int x = tsum;
  #pragma unroll
  for (int o=1;o<32;o<<=1){ int y=__shfl_up_sync(~0u,x,o); if(lane>=o) x+=y; }
  if (lane==31) ws[w]=x;
  __syncthreads();
  if (w==0){
    int y = ws[lane];
    #pragma unroll
    for (int o=1;o<32;o<<=1){ int z=__shfl_up_sync(~0u,y,o); if(lane>=o) y+=z; }
    ws[lane]=y;
  }
  __syncthreads();
  int base = (w ? ws[w-1] : 0) + x - tsum;
  #pragma unroll
  for (int i=0;i<32;i++){ off[t*32+i]=base; work[t*32+i]=base; base += v[i]; }
}

__global__ void k_scatter_both(const float* __restrict__ atom_xyz,
                               const float* __restrict__ xyz){
  int i = blockIdx.x*blockDim.x + threadIdx.x;
  if (i < M_AT){
    int b = bucket_of(atom_xyz[i*3], atom_xyz[i*3+1], atom_xyz[i*3+2]);
    g_aperm[atomicAdd(&g_awork[b], 1)] = i;
  } else if (i < M_AT + N_PTS){
    int p = i - M_AT;
    int b = bucket_of(xyz[p*3], xyz[p*3+1], xyz[p*3+2]);
    g_pperm[atomicAdd(&g_pwork[b], 1)] = p;
  }
}

// ---- transform_types MLP + atom packing (into sorted slots) ----
__global__ void __launch_bounds__(256) k_prep(
    const float* __restrict__ atom_types, const float* __restrict__ atom_xyz,
    const float* __restrict__ Wt1, const float* __restrict__ bt1,
    const float* __restrict__ Wt2, const float* __restrict__ bt2,
    const float* __restrict__ Wt3, const float* __restrict__ bt3){
  __shared__ float sW[3][D][D];
  __shared__ float sb[3][D];
  __shared__ float s_row[D][D+1];
  int tid = threadIdx.x;
  sW[0][tid>>4][tid&15] = Wt1[tid];
  sW[1][tid>>4][tid&15] = Wt2[tid];
  sW[2][tid>>4][tid&15] = Wt3[tid];
  if (tid < D){ sb[0][tid]=bt1[tid]; sb[1][tid]=bt2[tid]; sb[2][tid]=bt3[tid]; }
  __syncthreads();
  int r = tid>>4, d = tid&15;
  int slot = blockIdx.x*16 + r;
  int atom = g_aperm[slot];
  float v = atom_types[atom*D+d];
  #pragma unroll
  for (int L=0; L<3; L++){
    s_row[r][d] = v;
    __syncthreads();
    float acc = sb[L][d];
    #pragma unroll
    for (int i=0;i<D;i++) acc = fmaf(s_row[r][i], sW[L][i][d], acc);
    v = lrelu(acc);
    __syncthreads();
  }
  ((float*)g_t4)[slot*D+d] = v;
  if (d == 0){
    float x = atom_xyz[atom*3+0], y = atom_xyz[atom*3+1], z = atom_xyz[atom*3+2];
    g_atoms[slot] = make_float4(x, y, z, x*x + y*y + z*z);
  }
}

// insert-scan over a contiguous sorted-atom range [st,en)
#define SCAN_RUN(st, en)                                              \
  for (int _i=(st); _i<(en); _i++){                                   \
    float4 a = __ldg(&g_atoms[_i]);                                   \
    float v = fmaf(qx, a.x, a.w);                                     \
    v = fmaf(qy, a.y, v);                                             \
    v = fmaf(qz, a.z, v);                                             \
    if (v < bd[KNN-1]){                                               \
      bd[KNN-1] = v; bi[KNN-1] = _i;                                  \
      _Pragma("unroll")                                               \
      for (int j=KNN-1; j>0; j--){                                    \
        bool sw = bd[j] < bd[j-1];                                    \
        float tv = sw ? bd[j-1] : bd[j];                              \
        bd[j-1]  = sw ? bd[j] : bd[j-1];                              \
        bd[j]    = tv;                                                \
        int ti   = sw ? bi[j-1] : bi[j];                              \
        bi[j-1]  = sw ? bi[j] : bi[j-1];                              \
        bi[j]    = ti;                                                \
      }                                                               \
    }                                                                 \
  }

// ---- exact grid kNN: one thread per point, expanding Chebyshev shells ----
__global__ void __launch_bounds__(256) k_knn(const float* __restrict__ xyz){
  int w    = blockIdx.x*8 + (threadIdx.x>>5);
  int lane = threadIdx.x & 31;
  int sw_  = (w & 7)*NBLK_K + (w >> 3);     // shuffle warps for load balance
  int slot = sw_*32 + lane;
  if (slot >= N_PTS) return;
  int pt = g_pperm[slot];
  float px = xyz[pt*3+0], py = xyz[pt*3+1], pz = xyz[pt*3+2];
  float sx = px*px + py*py + pz*pz;
  float qx = -2.f*px, qy = -2.f*py, qz = -2.f*pz;
  int cx = cell1(px), cy = cell1(py), cz = cell1(pz);

  float bd[KNN]; int bi[KNN];
  #pragma unroll
  for (int j=0;j<KNN;j++){ bd[j] = 3.4e38f; bi[j] = 0; }

  for (int s=0; s<=31; s++){
    int xlo=max(cx-s,0), xhi=min(cx+s,31);
    int ylo=max(cy-s,0), yhi=min(cy+s,31);
    int zlo=max(cz-s,0), zhi=min(cz+s,31);
    for (int ix=xlo; ix<=xhi; ix++){
      int adx = abs(ix-cx);
      for (int iy=ylo; iy<=yhi; iy++){
        int m = max(adx, abs(iy-cy));
        int bbase = (ix<<10) | (iy<<5);
        if (m == s){
          int blo = bbase|zlo, bhi = bbase|zhi;
          int st = g_aoff[blo], en = g_aoff[bhi] + g_acnt[bhi];
          SCAN_RUN(st, en)
        } else {
          if (cz-s >= 0){ int b = bbase|(cz-s); int st=g_aoff[b]; SCAN_RUN(st, st+g_acnt[b]) }
          if (cz+s <= 31){ int b = bbase|(cz+s); int st=g_aoff[b]; SCAN_RUN(st, st+g_acnt[b]) }
        }
      }
    }
    // whole grid processed?
    if (cx-s<=0 && cx+s>=31 && cy-s<=0 && cy+s>=31 && cz-s<=0 && cz+s>=31) break;
    // rigorous stop: unscanned atoms lie beyond a non-edge face of the cube
    float dm = 1e30f;
    if (cx-s > 0)  dm = fminf(dm, px - ((cx-s)*0.25f - 4.0f));
    if (cx+s < 31) dm = fminf(dm, ((cx+s+1)*0.25f - 4.0f) - px);
    if (cy-s > 0)  dm = fminf(dm, py - ((cy-s)*0.25f - 4.0f));
    if (cy+s < 31) dm = fminf(dm, ((cy+s+1)*0.25f - 4.0f) - py);
    if (cz-s > 0)  dm = fminf(dm, pz - ((cz-s)*0.25f - 4.0f));
    if (cz+s < 31) dm = fminf(dm, ((cz+s+1)*0.25f - 4.0f) - pz);
    if (bd[KNN-1] < 3.0e38f && bd[KNN-1] + sx <= dm*dm) break;
  }

  #pragma unroll
  for (int j=0;j<KNN;j++){
    int a = bi[j];
    float4 av = g_atoms[a];
    float dx = px-av.x, dy = py-av.y, dz = pz-av.z;
    float dist = dx*dx + dy*dy + dz*dz;     // exact recompute (as in reference)
    g_idx [pt*KNN+j] = a;                   // a = sorted slot; g_t4 is slot-indexed
    g_invd[pt*KNN+j] = 1.0f/dist;
  }
}

// ---- conv1 + leaky + bn1 stats (8 points per block-iteration) ----
__global__ void __launch_bounds__(256) k_conv1(const float* __restrict__ W1,
                                               const float* __restrict__ b1){
  __shared__ float s_f[128][20];
  __shared__ float s_red[16][17];
  int tid = threadIdx.x;
  int d = tid & 15;
  float Wc[D+1];
  #pragma unroll
  for (int i=0;i<=D;i++) Wc[i] = W1[i*D + d];
  float bb = b1[d];
  int rA = tid >> 1, hA = tid & 1;
  int gB = tid >> 4;
  float lsum = 0.f, lsq = 0.f;

  for (int grp = blockIdx.x; grp < N_PTS/8; grp += gridDim.x){
    int base = grp*8*KNN;
    {
      int rowg = base + rA;
      int a = g_idx[rowg];
      float4 v0 = g_t4[a*4 + hA*2 + 0];
      float4 v1 = g_t4[a*4 + hA*2 + 1];
      *(float4*)&s_f[rA][hA*8 + 0] = v0;
      *(float4*)&s_f[rA][hA*8 + 4] = v1;
      if (hA == 0) s_f[rA][16] = g_invd[rowg];
    }
    __syncthreads();
    #pragma unroll
    for (int s=0;s<8;s++){
      int r = gB*8 + s;
      float acc = bb;
      #pragma unroll
      for (int q=0;q<4;q++){
        float4 f = *(const float4*)&s_f[r][q*4];
        acc = fmaf(f.x, Wc[q*4+0], acc);
        acc = fmaf(f.y, Wc[q*4+1], acc);
        acc = fmaf(f.z, Wc[q*4+2], acc);
        acc = fmaf(f.w, Wc[q*4+3], acc);
      }
      acc = fmaf(s_f[r][16], Wc[16], acc);
      float h = lrelu(acc);
      ((float*)g_h1v)[(base + r)*D + d] = h;
      lsum += h; lsq = fmaf(h, h, lsq);
    }
    __syncthreads();
  }
  s_red[gB][d] = lsum;
  __syncthreads();
  if (tid < D){
    float s = 0.f;
    #pragma unroll
    for (int j=0;j<16;j++) s += s_red[j][tid];
    atomicAdd(&g_stats[tid], (double)s);
  }
  __syncthreads();
  s_red[gB][d] = lsq;
  __syncthreads();
  if (tid < D){
    float s = 0.f;
    #pragma unroll
    for (int j=0;j<16;j++) s += s_red[j][tid];
    atomicAdd(&g_stats[D+tid], (double)s);
  }
}

// ---- BN finalize ----
__global__ void k_fin(const float* __restrict__ gma, const float* __restrict__ bet,
                      int stage){
  int d = threadIdx.x;
  if (d >= D) return;
  double s  = g_stats[stage*2*D + d];
  double sq = g_stats[stage*2*D + D + d];
  double mean = s / (double)NK;
  double var  = sq / (double)NK - mean*mean;
  float inv = (float)(1.0 / sqrt(var + BN_EPS));
  float Av = inv * gma[d];
  float Bv = bet[d] - (float)mean * Av;
  if (stage == 0){ ((float*)g_A1v)[d]=Av; ((float*)g_B1v)[d]=Bv; }
  else           { ((float*)g_A2v)[d]=Av; ((float*)g_B2v)[d]=Bv; }
}

// ---- bn1 apply + K-sum pool + conv2 + leaky + bn2 stats ----
__global__ void __launch_bounds__(256) k_stage2(const float* __restrict__ W2,
                                                const float* __restrict__ b2){
  __shared__ float s_f[128][20];
  __shared__ float s_red[16][17];
  int tid = threadIdx.x;
  int d = tid & 15;
  float Wc[D];
  #pragma unroll
  for (int i=0;i<D;i++) Wc[i] = W2[i*D + d];
  float bb = b2[d];
  int rA = tid >> 1, hA = tid & 1;
  float4 Aq0 = g_A1v[hA*2], Aq1 = g_A1v[hA*2+1];
  float4 Bq0 = g_B1v[hA*2], Bq1 = g_B1v[hA*2+1];
  int gB = tid >> 4;
  int pP = tid >> 4, dP = tid & 15;
  float lsum = 0.f, lsq = 0.f;

  for (int grp = blockIdx.x; grp < N_PTS/8; grp += gridDim.x){
    int base = grp*8*KNN;
    {
      int rowg = base + rA;
      float4 v0 = g_h1v[rowg*4 + hA*2 + 0];
      float4 v1 = g_h1v[rowg*4 + hA*2 + 1];
      float4 f0, f1;
      f0.x = fmaf(v0.x, Aq0.x, Bq0.x); f0.y = fmaf(v0.y, Aq0.y, Bq0.y);
      f0.z = fmaf(v0.z, Aq0.z, Bq0.z); f0.w = fmaf(v0.w, Aq0.w, Bq0.w);
      f1.x = fmaf(v1.x, Aq1.x, Bq1.x); f1.y = fmaf(v1.y, Aq1.y, Bq1.y);
      f1.z = fmaf(v1.z, Aq1.z, Bq1.z); f1.w = fmaf(v1.w, Aq1.w, Bq1.w);
      *(float4*)&s_f[rA][hA*8 + 0] = f0;
      *(float4*)&s_f[rA][hA*8 + 4] = f1;
    }
    __syncthreads();
    #pragma unroll
    for (int s=0;s<8;s++){
      int r = gB*8 + s;
      float acc = bb;
      #pragma unroll
      for (int q=0;q<4;q++){
        float4 f = *(const float4*)&s_f[r][q*4];
        acc = fmaf(f.x, Wc[q*4+0], acc);
        acc = fmaf(f.y, Wc[q*4+1], acc);
        acc = fmaf(f.z, Wc[q*4+2], acc);
        acc = fmaf(f.w, Wc[q*4+3], acc);
      }
      float h = lrelu(acc);
      ((float*)g_h2v)[(base + r)*D + d] = h;
      lsum += h; lsq = fmaf(h, h, lsq);
    }
    if (tid < 128){
      float s = 0.f;
      #pragma unroll
      for (int k=0;k<KNN;k++) s += s_f[pP*16 + k][dP];
      g_fx1[(grp*8 + pP)*D + dP] = s;
    }
    __syncthreads();
  }
  s_red[gB][d] = lsum;
  __syncthreads();
  if (tid < D){
    float s = 0.f;
    #pragma unroll
    for (int j=0;j<16;j++) s += s_red[j][tid];
    atomicAdd(&g_stats[2*D+tid], (double)s);
  }
  __syncthreads();
  s_red[gB][d] = lsq;
  __syncthreads();
  if (tid < D){
    float s = 0.f;
    #pragma unroll
    for (int j=0;j<16;j++) s += s_red[j][tid];
    atomicAdd(&g_stats[3*D+tid], (double)s);
  }
}

// ---- bn2 apply + K-sum + concat + final Linear(32,16) ----
__global__ void __launch_bounds__(256) k_stage3(const float* __restrict__ W3,
                                                const float* __restrict__ b3,
                                                float* __restrict__ out){
  __shared__ float sW[2*D][D];
  __shared__ float s1[16][17];
  __shared__ float s2[16][17];
  int tid = threadIdx.x;
  for (int i=tid; i<2*D*D; i+=256) sW[i>>4][i&15] = W3[i];
  int p = tid >> 4, d = tid & 15;
  float a2 = ((const float*)g_A2v)[d];
  float b2k = 16.f * ((const float*)g_B2v)[d];
  float bb = b3[d];
  __syncthreads();

  for (int grp = blockIdx.x; grp < N_PTS/16; grp += gridDim.x){
    int P0 = grp*16;
    s1[p][d] = g_fx1[(P0+p)*D + d];
    float s = 0.f;
    const float* h2 = (const float*)g_h2v;
    #pragma unroll
    for (int k=0;k<KNN;k++) s += h2[((P0+p)*KNN + k)*D + d];
    s2[p][d] = fmaf(a2, s, b2k);
    __syncthreads();
    float acc = bb;
    #pragma unroll
    for (int i=0;i<D;i++) acc = fmaf(s1[p][i], sW[i][d], acc);
    #pragma unroll
    for (int i=0;i<D;i++) acc = fmaf(s2[p][i], sW[D+i][d], acc);
    out[(P0+p)*D + d] = acc;
    __syncthreads();
  }
}

extern "C" void kernel_launch(void* const* d_in, const int* in_sizes, int n_in,
                              void* d_out, int out_size){
  const float* xyz        = (const float*)d_in[0];
  const float* atom_xyz   = (const float*)d_in[1];
  const float* atom_types = (const float*)d_in[2];
  const float* Wt1 = (const float*)d_in[3];  const float* bt1 = (const float*)d_in[4];
  const float* Wt2 = (const float*)d_in[5];  const float* bt2 = (const float*)d_in[6];
  const float* Wt3 = (const float*)d_in[7];  const float* bt3 = (const float*)d_in[8];
  const float* W1  = (const float*)d_in[9];  const float* b1  = (const float*)d_in[10];
  const float* W2  = (const float*)d_in[11]; const float* b2  = (const float*)d_in[12];
  const float* W3  = (const float*)d_in[13]; const float* b3  = (const float*)d_in[14];
  const float* g1  = (const float*)d_in[15]; const float* be1 = (const float*)d_in[16];
  const float* g2  = (const float*)d_in[17]; const float* be2 = (const float*)d_in[18];
  float* out = (float*)d_out;

  k_zero        <<<(2*NBKT+1023)/1024, 1024>>>();
  k_count_both  <<<(M_AT+N_PTS+255)/256, 256>>>(atom_xyz, xyz);
  k_scan2       <<<2, 1024>>>();
  k_scatter_both<<<(M_AT+N_PTS+255)/256, 256>>>(atom_xyz, xyz);
  k_prep        <<<M_AT/16, 256>>>(atom_types, atom_xyz, Wt1,bt1, Wt2,bt2, Wt3,bt3);
  k_knn         <<<NBLK_K, 256>>>(xyz);
  k_conv1       <<<592, 256>>>(W1, b1);
  k_fin         <<<1, 16>>>(g1, be1, 0);
  k_stage2      <<<592, 256>>>(W2, b2);
  k_fin         <<<1, 16>>>(g2, be2, 1);
  k_stage3      <<<592, 256>>>(W3, b3, out);
}

// round 12
// speedup vs baseline: 2.0152x; 2.0152x over previous
#include <cuda_runtime.h>
#include <math.h>

#define N_PTS 30000
#define M_AT  8000
#define D     16
#define KNN   16
#define NK    (N_PTS*KNN)
#define BN_EPS 1e-5
#define SLOPE 0.2f
#define NC    16
#define NBKT  (NC*NC*NC)                     // 4096 cells of 0.5
#define NWARP ((N_PTS + 31) / 32)            // 938
#define NBLK_K 118                           // ceil(944 warps / 8)

// ---- scratch (device globals) ----
__device__ float4 g_atoms[M_AT];          // sorted: x,y,z,|y|^2
__device__ float4 g_t4[M_AT*4];           // sorted transformed atom feats
__device__ int    g_aperm[M_AT];          // sorted slot -> original atom
__device__ int    g_pperm[N_PTS];         // sorted slot -> original point
__device__ int    g_acnt[NBKT], g_aoff[NBKT], g_awork[NBKT];
__device__ int    g_pcnt[NBKT], g_poff[NBKT], g_pwork[NBKT];
__device__ int    g_idx[NK];              // knn indices (sorted-slot space)
__device__ float  g_invd[NK];
__device__ float4 g_h1v[NK*4];
__device__ float4 g_h2v[NK*4];
__device__ float  g_fx1[N_PTS*D];
__device__ double g_stats[4*D];
__device__ float4 g_A1v[4], g_B1v[4], g_A2v[4], g_B2v[4];

__device__ __forceinline__ float lrelu(float x){ return x > 0.f ? x : SLOPE*x; }

__device__ __forceinline__ int cell1(float x){
  return (int)fminf(fmaxf((x+4.f)*2.f, 0.f), 15.f);
}
__device__ __forceinline__ int bucket_of(float x, float y, float z){
  return (cell1(x)<<8) | (cell1(y)<<4) | cell1(z);
}

// ---- zero counters + stats ----
__global__ void __launch_bounds__(1024) k_zero(){
  int i = blockIdx.x*1024 + threadIdx.x;
  if (i < NBKT) g_acnt[i] = 0; else if (i < 2*NBKT) g_pcnt[i-NBKT] = 0;
  if (blockIdx.x == 0 && threadIdx.x < 4*D) g_stats[threadIdx.x] = 0.0;
}

// ---- count atoms and points in one launch ----
__global__ void k_count_both(const float* __restrict__ atom_xyz,
                             const float* __restrict__ xyz){
  int i = blockIdx.x*blockDim.x + threadIdx.x;
  if (i < M_AT){
    atomicAdd(&g_acnt[bucket_of(atom_xyz[i*3], atom_xyz[i*3+1], atom_xyz[i*3+2])], 1);
  } else if (i < M_AT + N_PTS){
    int p = i - M_AT;
    atomicAdd(&g_pcnt[bucket_of(xyz[p*3], xyz[p*3+1], xyz[p*3+2])], 1);
  }
}

// ---- exclusive scan of 4096 ints; block 0 = atoms, block 1 = points ----
__global__ void __launch_bounds__(1024) k_scan2(){
  const int* cnt = blockIdx.x ? g_pcnt : g_acnt;
  int* off  = blockIdx.x ? g_poff  : g_aoff;
  int* work = blockIdx.x ? g_pwork : g_awork;
  __shared__ int ws[32];
  int t = threadIdx.x;
  int v0=cnt[t*4], v1=cnt[t*4+1], v2=cnt[t*4+2], v3=cnt[t*4+3];
  int tsum = v0+v1+v2+v3;
  int lane = t&31, w = t>>5;
  int x = tsum;
  #pragma unroll
  for (int o=1;o<32;o<<=1){ int y=__shfl_up_sync(~0u,x,o); if(lane>=o) x+=y; }
  if (lane==31) ws[w]=x;
  __syncthreads();
  if (w==0){
    int y = ws[lane];
    #pragma unroll
    for (int o=1;o<32;o<<=1){ int z=__shfl_up_sync(~0u,y,o); if(lane>=o) y+=z; }
    ws[lane]=y;
  }
  __syncthreads();
  int base = (w ? ws[w-1] : 0) + x - tsum;
  off[t*4+0]=base;          work[t*4+0]=base;
  off[t*4+1]=base+v0;       work[t*4+1]=base+v0;
  off[t*4+2]=base+v0+v1;    work[t*4+2]=base+v0+v1;
  off[t*4+3]=base+v0+v1+v2; work[t*4+3]=base+v0+v1+v2;
}

__global__ void k_scatter_both(const float* __restrict__ atom_xyz,
                               const float* __restrict__ xyz){
  int i = blockIdx.x*blockDim.x + threadIdx.x;
  if (i < M_AT){
    int b = bucket_of(atom_xyz[i*3], atom_xyz[i*3+1], atom_xyz[i*3+2]);
    g_aperm[atomicAdd(&g_awork[b], 1)] = i;
  } else if (i < M_AT + N_PTS){
    int p = i - M_AT;
    int b = bucket_of(xyz[p*3], xyz[p*3+1], xyz[p*3+2]);
    g_pperm[atomicAdd(&g_pwork[b], 1)] = p;
  }
}

// ---- transform_types MLP + atom packing (into sorted slots) ----
__global__ void __launch_bounds__(256) k_prep(
    const float* __restrict__ atom_types, const float* __restrict__ atom_xyz,
    const float* __restrict__ Wt1, const float* __restrict__ bt1,
    const float* __restrict__ Wt2, const float* __restrict__ bt2,
    const float* __restrict__ Wt3, const float* __restrict__ bt3){
  __shared__ float sW[3][D][D];
  __shared__ float sb[3][D];
  __shared__ float s_row[D][D+1];
  int tid = threadIdx.x;
  sW[0][tid>>4][tid&15] = Wt1[tid];
  sW[1][tid>>4][tid&15] = Wt2[tid];
  sW[2][tid>>4][tid&15] = Wt3[tid];
  if (tid < D){ sb[0][tid]=bt1[tid]; sb[1][tid]=bt2[tid]; sb[2][tid]=bt3[tid]; }
  __syncthreads();
  int r = tid>>4, d = tid&15;
  int slot = blockIdx.x*16 + r;
  int atom = g_aperm[slot];
  float v = atom_types[atom*D+d];
  #pragma unroll
  for (int L=0; L<3; L++){
    s_row[r][d] = v;
    __syncthreads();
    float acc = sb[L][d];
    #pragma unroll
    for (int i=0;i<D;i++) acc = fmaf(s_row[r][i], sW[L][i][d], acc);
    v = lrelu(acc);
    __syncthreads();
  }
  ((float*)g_t4)[slot*D+d] = v;
  if (d == 0){
    float x = atom_xyz[atom*3+0], y = atom_xyz[atom*3+1], z = atom_xyz[atom*3+2];
    g_atoms[slot] = make_float4(x, y, z, x*x + y*y + z*z);
  }
}

// insert-scan over a contiguous sorted-atom range [st,en)
#define SCAN_RUN(st, en)                                              \
  for (int _i=(st); _i<(en); _i++){                                   \
    float4 a = __ldg(&g_atoms[_i]);                                   \
    float v = fmaf(qx, a.x, a.w);                                     \
    v = fmaf(qy, a.y, v);                                             \
    v = fmaf(qz, a.z, v);                                             \
    if (v < bd[KNN-1]){                                               \
      bd[KNN-1] = v; bi[KNN-1] = _i;                                  \
      _Pragma("unroll")                                               \
      for (int j=KNN-1; j>0; j--){                                    \
        bool sw = bd[j] < bd[j-1];                                    \
        float tv = sw ? bd[j-1] : bd[j];                              \
        bd[j-1]  = sw ? bd[j] : bd[j-1];                              \
        bd[j]    = tv;                                                \
        int ti   = sw ? bi[j-1] : bi[j];                              \
        bi[j-1]  = sw ? bi[j] : bi[j-1];                              \
        bi[j]    = ti;                                                \
      }                                                               \
    }                                                                 \
  }

// ---- exact grid kNN: one thread per point, expanding Chebyshev shells,
//      sphere-trimmed z-runs ----
__global__ void __launch_bounds__(256) k_knn(const float* __restrict__ xyz){
  int w    = blockIdx.x*8 + (threadIdx.x>>5);
  int lane = threadIdx.x & 31;
  int sw_  = (w & 7)*NBLK_K + (w >> 3);     // shuffle warps for load balance
  int slot = sw_*32 + lane;
  if (slot >= N_PTS) return;
  int pt = g_pperm[slot];
  float px = xyz[pt*3+0], py = xyz[pt*3+1], pz = xyz[pt*3+2];
  float sx = px*px + py*py + pz*pz;
  float qx = -2.f*px, qy = -2.f*py, qz = -2.f*pz;
  int cx = cell1(px), cy = cell1(py), cz = cell1(pz);

  float bd[KNN]; int bi[KNN];
  #pragma unroll
  for (int j=0;j<KNN;j++){ bd[j] = 3.4e38f; bi[j] = 0; }

  for (int s=0; s<=15; s++){
    int xlo=max(cx-s,0), xhi=min(cx+s,15);
    int ylo=max(cy-s,0), yhi=min(cy+s,15);
    int zlo=max(cz-s,0), zhi=min(cz+s,15);
    for (int ix=xlo; ix<=xhi; ix++){
      int adx = abs(ix-cx);
      // column x-face min distance (exact lower bound; edge cells extend to inf)
      float dxm = (ix==cx) ? 0.f
                : (ix>cx ? (ix*0.5f-4.f)-px : px-((ix+1)*0.5f-4.f));
      for (int iy=ylo; iy<=yhi; iy++){
        int m = max(adx, abs(iy-cy));
        float dym = (iy==cy) ? 0.f
                  : (iy>cy ? (iy*0.5f-4.f)-py : py-((iy+1)*0.5f-4.f));
        float cd2 = dxm*dxm + dym*dym;
        bool have = bd[KNN-1] < 3.0e38f;
        float budget = bd[KNN-1] + sx;      // current r16^2
        int tzlo = 0, tzhi = 15;
        if (have){
          if (cd2 > budget) continue;       // whole column beyond r16
          float dz = sqrtf(budget - cd2);
          tzlo = cell1(pz - dz);
          tzhi = cell1(pz + dz);
        }
        int bbase = (ix<<8) | (iy<<4);
        if (m == s){
          int zl = max(zlo, tzlo), zh = min(zhi, tzhi);
          if (zl > zh) continue;
          int blo = bbase|zl, bhi = bbase|zh;
          int st = g_aoff[blo], en = g_aoff[bhi] + g_acnt[bhi];
          SCAN_RUN(st, en)
        } else {
          int zm = cz - s, zp = cz + s;
          if (zm >= 0 && zm >= tzlo && zm <= tzhi){
            int b = bbase|zm; int st=g_aoff[b]; SCAN_RUN(st, st+g_acnt[b])
          }
          if (zp <= 15 && zp >= tzlo && zp <= tzhi){
            int b = bbase|zp; int st=g_aoff[b]; SCAN_RUN(st, st+g_acnt[b])
          }
        }
      }
    }
    // whole grid processed?
    if (cx-s<=0 && cx+s>=15 && cy-s<=0 && cy+s>=15 && cz-s<=0 && cz+s>=15) break;
    // rigorous stop: unscanned atoms lie beyond a non-edge face of the cube
    float dm = 1e30f;
    if (cx-s > 0)  dm = fminf(dm, px - ((cx-s)*0.5f - 4.0f));
    if (cx+s < 15) dm = fminf(dm, ((cx+s+1)*0.5f - 4.0f) - px);
    if (cy-s > 0)  dm = fminf(dm, py - ((cy-s)*0.5f - 4.0f));
    if (cy+s < 15) dm = fminf(dm, ((cy+s+1)*0.5f - 4.0f) - py);
    if (cz-s > 0)  dm = fminf(dm, pz - ((cz-s)*0.5f - 4.0f));
    if (cz+s < 15) dm = fminf(dm, ((cz+s+1)*0.5f - 4.0f) - pz);
    if (bd[KNN-1] < 3.0e38f && bd[KNN-1] + sx <= dm*dm) break;
  }

  #pragma unroll
  for (int j=0;j<KNN;j++){
    int a = bi[j];
    float4 av = g_atoms[a];
    float dx = px-av.x, dy = py-av.y, dz = pz-av.z;
    float dist = dx*dx + dy*dy + dz*dz;     // exact recompute (as in reference)
    g_idx [pt*KNN+j] = a;                   // a = sorted slot; g_t4 is slot-indexed
    g_invd[pt*KNN+j] = 1.0f/dist;
  }
}

// ---- conv1 + leaky + bn1 stats (8 points per block-iteration) ----
__global__ void __launch_bounds__(256) k_conv1(const float* __restrict__ W1,
                                               const float* __restrict__ b1){
  __shared__ float s_f[128][20];
  __shared__ float s_red[16][17];
  int tid = threadIdx.x;
  int d = tid & 15;
  float Wc[D+1];
  #pragma unroll
  for (int i=0;i<=D;i++) Wc[i] = W1[i*D + d];
  float bb = b1[d];
  int rA = tid >> 1, hA = tid & 1;
  int gB = tid >> 4;
  float lsum = 0.f, lsq = 0.f;

  for (int grp = blockIdx.x; grp < N_PTS/8; grp += gridDim.x){
    int base = grp*8*KNN;
    {
      int rowg = base + rA;
      int a = g_idx[rowg];
      float4 v0 = g_t4[a*4 + hA*2 + 0];
      float4 v1 = g_t4[a*4 + hA*2 + 1];
      *(float4*)&s_f[rA][hA*8 + 0] = v0;
      *(float4*)&s_f[rA][hA*8 + 4] = v1;
      if (hA == 0) s_f[rA][16] = g_invd[rowg];
    }
    __syncthreads();
    #pragma unroll
    for (int s=0;s<8;s++){
      int r = gB*8 + s;
      float acc = bb;
      #pragma unroll
      for (int q=0;q<4;q++){
        float4 f = *(const float4*)&s_f[r][q*4];
        acc = fmaf(f.x, Wc[q*4+0], acc);
        acc = fmaf(f.y, Wc[q*4+1], acc);
        acc = fmaf(f.z, Wc[q*4+2], acc);
        acc = fmaf(f.w, Wc[q*4+3], acc);
      }
      acc = fmaf(s_f[r][16], Wc[16], acc);
      float h = lrelu(acc);
      ((float*)g_h1v)[(base + r)*D + d] = h;
      lsum += h; lsq = fmaf(h, h, lsq);
    }
    __syncthreads();
  }
  s_red[gB][d] = lsum;
  __syncthreads();
  if (tid < D){
    float s = 0.f;
    #pragma unroll
    for (int j=0;j<16;j++) s += s_red[j][tid];
    atomicAdd(&g_stats[tid], (double)s);
  }
  __syncthreads();
  s_red[gB][d] = lsq;
  __syncthreads();
  if (tid < D){
    float s = 0.f;
    #pragma unroll
    for (int j=0;j<16;j++) s += s_red[j][tid];
    atomicAdd(&g_stats[D+tid], (double)s);
  }
}

// ---- BN finalize ----
__global__ void k_fin(const float* __restrict__ gma, const float* __restrict__ bet,
                      int stage){
  int d = threadIdx.x;
  if (d >= D) return;
  double s  = g_stats[stage*2*D + d];
  double sq = g_stats[stage*2*D + D + d];
  double mean = s / (double)NK;
  double var  = sq / (double)NK - mean*mean;
  float inv = (float)(1.0 / sqrt(var + BN_EPS));
  float Av = inv * gma[d];
  float Bv = bet[d] - (float)mean * Av;
  if (stage == 0){ ((float*)g_A1v)[d]=Av; ((float*)g_B1v)[d]=Bv; }
  else           { ((float*)g_A2v)[d]=Av; ((float*)g_B2v)[d]=Bv; }
}

// ---- bn1 apply + K-sum pool + conv2 + leaky + bn2 stats ----
__global__ void __launch_bounds__(256) k_stage2(const float* __restrict__ W2,
                                                const float* __restrict__ b2){
  __shared__ float s_f[128][20];
  __shared__ float s_red[16][17];
  int tid = threadIdx.x;
  int d = tid & 15;
  float Wc[D];
  #pragma unroll
  for (int i=0;i<D;i++) Wc[i] = W2[i*D + d];
  float bb = b2[d];
  int rA = tid >> 1, hA = tid & 1;
  float4 Aq0 = g_A1v[hA*2], Aq1 = g_A1v[hA*2+1];
  float4 Bq0 = g_B1v[hA*2], Bq1 = g_B1v[hA*2+1];
  int gB = tid >> 4;
  int pP = tid >> 4, dP = tid & 15;
  float lsum = 0.f, lsq = 0.f;

  for (int grp = blockIdx.x; grp < N_PTS/8; grp += gridDim.x){
    int base = grp*8*KNN;
    {
      int rowg = base + rA;
      float4 v0 = g_h1v[rowg*4 + hA*2 + 0];
      float4 v1 = g_h1v[rowg*4 + hA*2 + 1];
      float4 f0, f1;
      f0.x = fmaf(v0.x, Aq0.x, Bq0.x); f0.y = fmaf(v0.y, Aq0.y, Bq0.y);
      f0.z = fmaf(v0.z, Aq0.z, Bq0.z); f0.w = fmaf(v0.w, Aq0.w, Bq0.w);
      f1.x = fmaf(v1.x, Aq1.x, Bq1.x); f1.y = fmaf(v1.y, Aq1.y, Bq1.y);
      f1.z = fmaf(v1.z, Aq1.z, Bq1.z); f1.w = fmaf(v1.w, Aq1.w, Bq1.w);
      *(float4*)&s_f[rA][hA*8 + 0] = f0;
      *(float4*)&s_f[rA][hA*8 + 4] = f1;
    }
    __syncthreads();
    #pragma unroll
    for (int s=0;s<8;s++){
      int r = gB*8 + s;
      float acc = bb;
      #pragma unroll
      for (int q=0;q<4;q++){
        float4 f = *(const float4*)&s_f[r][q*4];
        acc = fmaf(f.x, Wc[q*4+0], acc);
        acc = fmaf(f.y, Wc[q*4+1], acc);
        acc = fmaf(f.z, Wc[q*4+2], acc);
        acc = fmaf(f.w, Wc[q*4+3], acc);
      }
      float h = lrelu(acc);
      ((float*)g_h2v)[(base + r)*D + d] = h;
      lsum += h; lsq = fmaf(h, h, lsq);
    }
    if (tid < 128){
      float s = 0.f;
      #pragma unroll
      for (int k=0;k<KNN;k++) s += s_f[pP*16 + k][dP];
      g_fx1[(grp*8 + pP)*D + dP] = s;
    }
    __syncthreads();
  }
  s_red[gB][d] = lsum;
  __syncthreads();
  if (tid < D){
    float s = 0.f;
    #pragma unroll
    for (int j=0;j<16;j++) s += s_red[j][tid];
    atomicAdd(&g_stats[2*D+tid], (double)s);
  }
  __syncthreads();
  s_red[gB][d] = lsq;
  __syncthreads();
  if (tid < D){
    float s = 0.f;
    #pragma unroll
    for (int j=0;j<16;j++) s += s_red[j][tid];
    atomicAdd(&g_stats[3*D+tid], (double)s);
  }
}

// ---- bn2 apply + K-sum + concat + final Linear(32,16) ----
__global__ void __launch_bounds__(256) k_stage3(const float* __restrict__ W3,
                                                const float* __restrict__ b3,
                                                float* __restrict__ out){
  __shared__ float sW[2*D][D];
  __shared__ float s1[16][17];
  __shared__ float s2[16][17];
  int tid = threadIdx.x;
  for (int i=tid; i<2*D*D; i+=256) sW[i>>4][i&15] = W3[i];
  int p = tid >> 4, d = tid & 15;
  float a2 = ((const float*)g_A2v)[d];
  float b2k = 16.f * ((const float*)g_B2v)[d];
  float bb = b3[d];
  __syncthreads();

  for (int grp = blockIdx.x; grp < N_PTS/16; grp += gridDim.x){
    int P0 = grp*16;
    s1[p][d] = g_fx1[(P0+p)*D + d];
    float s = 0.f;
    const float* h2 = (const float*)g_h2v;
    #pragma unroll
    for (int k=0;k<KNN;k++) s += h2[((P0+p)*KNN + k)*D + d];
    s2[p][d] = fmaf(a2, s, b2k);
    __syncthreads();
    float acc = bb;
    #pragma unroll
    for (int i=0;i<D;i++) acc = fmaf(s1[p][i], sW[i][d], acc);
    #pragma unroll
    for (int i=0;i<D;i++) acc = fmaf(s2[p][i], sW[D+i][d], acc);
    out[(P0+p)*D + d] = acc;
    __syncthreads();
  }
}

extern "C" void kernel_launch(void* const* d_in, const int* in_sizes, int n_in,
                              void* d_out, int out_size){
  const float* xyz        = (const float*)d_in[0];
  const float* atom_xyz   = (const float*)d_in[1];
  const float* atom_types = (const float*)d_in[2];
  const float* Wt1 = (const float*)d_in[3];  const float* bt1 = (const float*)d_in[4];
  const float* Wt2 = (const float*)d_in[5];  const float* bt2 = (const float*)d_in[6];
  const float* Wt3 = (const float*)d_in[7];  const float* bt3 = (const float*)d_in[8];
  const float* W1  = (const float*)d_in[9];  const float* b1  = (const float*)d_in[10];
  const float* W2  = (const float*)d_in[11]; const float* b2  = (const float*)d_in[12];
  const float* W3  = (const float*)d_in[13]; const float* b3  = (const float*)d_in[14];
  const float* g1  = (const float*)d_in[15]; const float* be1 = (const float*)d_in[16];
  const float* g2  = (const float*)d_in[17]; const float* be2 = (const float*)d_in[18];
  float* out = (float*)d_out;

  k_zero        <<<(2*NBKT+1023)/1024, 1024>>>();
  k_count_both  <<<(M_AT+N_PTS+255)/256, 256>>>(atom_xyz, xyz);
  k_scan2       <<<2, 1024>>>();
  k_scatter_both<<<(M_AT+N_PTS+255)/256, 256>>>(atom_xyz, xyz);
  k_prep        <<<M_AT/16, 256>>>(atom_types, atom_xyz, Wt1,bt1, Wt2,bt2, Wt3,bt3);
  k_knn         <<<NBLK_K, 256>>>(xyz);
  k_conv1       <<<592, 256>>>(W1, b1);
  k_fin         <<<1, 16>>>(g1, be1, 0);
  k_stage2      <<<592, 256>>>(W2, b2);
  k_fin         <<<1, 16>>>(g2, be2, 1);
  k_stage3      <<<592, 256>>>(W3, b3, out);
}